// round 4
// baseline (speedup 1.0000x reference)
#include <cuda_runtime.h>
#include <cstdint>

#define BATCH 512
#define N 256
constexpr float FINF = 1e30f;

// Scratch: transposed + sanitized + pad-zeroed cost matrices (128 MiB, static).
__device__ float g_P[(size_t)BATCH * N * N];
__device__ int   g_nk[BATCH];

// order-preserving float->uint key (ascending), with -0 canonicalized to +0
__device__ __forceinline__ unsigned fkey(float f) {
    unsigned b = __float_as_uint(f);
    unsigned k = (b & 0x80000000u) ? ~b : (b | 0x80000000u);
    k += (k == 0x7FFFFFFFu);  // -0 -> +0 key (integer op, fast-math-proof)
    return k;
}
__device__ __forceinline__ float fkey_inv(unsigned k) {
    unsigned b = (k & 0x80000000u) ? (k ^ 0x80000000u) : ~k;
    return __uint_as_float(b);
}

// ---------------------------------------------------------------------------
// Kernel 1: n_k[b] = count of nonzero mask words (bool widened to i32 or f32).
// ---------------------------------------------------------------------------
__global__ void nk_kernel(const unsigned int* __restrict__ mask) {
    int b = blockIdx.x;
    int t = threadIdx.x;
    int v = (mask[b * N + t] != 0u) ? 1 : 0;
#pragma unroll
    for (int off = 16; off; off >>= 1) v += __shfl_xor_sync(0xffffffffu, v, off);
    __shared__ int s[8];
    if ((t & 31) == 0) s[t >> 5] = v;
    __syncthreads();
    if (t == 0) {
        int tot = 0;
#pragma unroll
        for (int w = 0; w < 8; w++) tot += s[w];
        g_nk[b] = tot;
    }
}

// ---------------------------------------------------------------------------
// Kernel 2: P[b][i][j] = sanitize(costs[b][j][i]) for i < n_k[b], else 0
// ---------------------------------------------------------------------------
__global__ void transpose_kernel(const float* __restrict__ costs) {
    __shared__ float tile[32][33];
    int b  = blockIdx.z;
    int i0 = blockIdx.x * 32;
    int j0 = blockIdx.y * 32;
    int tx = threadIdx.x, ty = threadIdx.y;  // 32 x 8
    const float* src = costs + (size_t)b * N * N;
    float*       dst = g_P   + (size_t)b * N * N;
#pragma unroll
    for (int s = 0; s < 32; s += 8) {
        float x = src[(size_t)(j0 + ty + s) * N + (i0 + tx)];
        unsigned bits = __float_as_uint(x);
        if ((bits & 0x7f800000u) == 0x7f800000u) x = 1e6f;  // nan or +-inf
        tile[ty + s][tx] = x;
    }
    __syncthreads();
    int nkb = g_nk[b];
#pragma unroll
    for (int s = 0; s < 32; s += 8) {
        int i = i0 + ty + s;
        dst[(size_t)i * N + (j0 + tx)] = (i < nkb) ? tile[tx][ty + s] : 0.0f;
    }
}

// ---------------------------------------------------------------------------
// Kernel 3: one warp per batch, JV shortest augmenting path.
// Lane l owns columns j = 8l..8l+7 (float4 x2 row loads).
// Argmin in order-preserving key space: per-lane IMNMX tree + ffs,
// cross-lane via two REDUX.SYNC.MIN. Tie-break = smallest j (== jnp argmin).
// Float arithmetic order replicates the JAX reference exactly.
// ---------------------------------------------------------------------------
__global__ void __launch_bounds__(32) solve_kernel(float* __restrict__ out) {
    const int b    = blockIdx.x;
    const int lane = threadIdx.x;
    const float* P = g_P + (size_t)b * N * N;
    const int nk   = g_nk[b];
    const unsigned KINF = fkey(FINF);

    __shared__ float u[N];
    __shared__ int   c4r[N];
    __shared__ int   r4c[N];
    __shared__ float shS[N];
    __shared__ int   shP[N];

    float v[8];
#pragma unroll
    for (int t = 0; t < 8; t++) {
        int idx = 8 * lane + t;
        u[idx] = 0.0f; c4r[idx] = -1; r4c[idx] = -1; v[t] = 0.0f;
    }
    __syncwarp();

    // prefetch row 0
    const float4* pr = (const float4*)P + lane * 2;
    float4 pf0 = pr[0], pf1 = pr[1];

    for (int cur = 0; cur < N; ++cur) {
        unsigned sk[8];   // shortest as keys
        float    sf[8];   // shortest as floats (exact, for dual updates)
        int      prow[8];
#pragma unroll
        for (int t = 0; t < 8; t++) { sk[t] = KINF; sf[t] = FINF; prow[t] = -1; }
        unsigned scMask = 0, srMask = 0;
        int   i      = cur;
        float minval = 0.0f;
        int   sink;
        float4 c0 = pf0, c1 = pf1;

        while (true) {
            if ((i >> 3) == lane) srMask |= 1u << (i & 7);  // SR[i] = true
            float ui = u[i];
            float cj[8] = {c0.x, c0.y, c0.z, c0.w, c1.x, c1.y, c1.z, c1.w};

            unsigned mk[8];
#pragma unroll
            for (int t = 0; t < 8; t++) {
                if (!((scMask >> t) & 1u)) {
                    // exact reference op order: ((minval + cost) - u[i]) - v[j]
                    float r = ((minval + cj[t]) - ui) - v[t];
                    unsigned rk = fkey(r);
                    if (rk < sk[t]) { sk[t] = rk; sf[t] = r; prow[t] = i; }
                    mk[t] = sk[t];
                } else {
                    mk[t] = KINF;  // masked (SC)
                }
            }
            // per-lane min key (flat int-min tree)
            unsigned a0 = min(mk[0], mk[1]), a1 = min(mk[2], mk[3]);
            unsigned a2 = min(mk[4], mk[5]), a3 = min(mk[6], mk[7]);
            unsigned m  = min(min(a0, a1), min(a2, a3));
            // first t achieving m
            unsigned tmask = 0;
#pragma unroll
            for (int t = 0; t < 8; t++) tmask |= (mk[t] == m) ? (1u << t) : 0u;
            int myJ = 8 * lane + (__ffs(tmask) - 1);
            // cross-lane argmin (min key, then min j among tied lanes)
            unsigned gmin = __reduce_min_sync(0xffffffffu, m);
            unsigned jc   = (m == gmin) ? (unsigned)myJ : 0xFFFFFFFFu;
            int jmin      = (int)__reduce_min_sync(0xffffffffu, jc);
            minval = fkey_inv(gmin);

            if ((jmin >> 3) == lane) scMask |= 1u << (jmin & 7);  // SC[jmin] = true
            int nxt = r4c[jmin];
            if (nxt < 0) { sink = jmin; break; }
            i = nxt;
            const float4* p4 = (const float4*)(P + (size_t)i * N) + lane * 2;
            c0 = p4[0]; c1 = p4[1];
        }

        // prefetch next Dijkstra's first row (hidden behind epilogue below)
        if (cur + 1 < N) {
            const float4* p4 = (const float4*)(P + (size_t)(cur + 1) * N) + lane * 2;
            pf0 = p4[0]; pf1 = p4[1];
        }

        // dump per-column state (vectorized STS)
        {
            float4* s4 = (float4*)(shS + 8 * lane);
            s4[0] = make_float4(sf[0], sf[1], sf[2], sf[3]);
            s4[1] = make_float4(sf[4], sf[5], sf[6], sf[7]);
            int4* p4s = (int4*)(shP + 8 * lane);
            p4s[0] = make_int4(prow[0], prow[1], prow[2], prow[3]);
            p4s[1] = make_int4(prow[4], prow[5], prow[6], prow[7]);
        }
        __syncwarp();

        // dual updates (reads c4r BEFORE augmentation, as in reference)
#pragma unroll
        for (int t = 0; t < 8; t++) {
            int row = 8 * lane + t;
            if (row == cur) {
                u[row] = u[row] + minval;
            } else if ((srMask >> t) & 1u) {
                int c  = c4r[row];
                u[row] = u[row] + (minval - shS[c]);
            }
            if ((scMask >> t) & 1u) v[t] = v[t] - (minval - sf[t]);
        }
        __syncwarp();

        // augment along alternating path back to cur (lane 0)
        if (lane == 0) {
            int j = sink;
            while (true) {
                int ii  = shP[j];
                r4c[j]  = ii;
                int jn  = c4r[ii];
                c4r[ii] = j;
                j = jn;
                if (ii == cur) break;
            }
        }
        __syncwarp();
    }

    // Output (float32): valid rows -> assigned column; padded rows -> unused
    // prediction indices ascending (reference's argsort fill).
    if (lane == 0) {
        float* ob = out + b * N;
        int cnt = 0;
        for (int j = 0; j < N; j++)
            if (r4c[j] >= nk) ob[nk + cnt++] = (float)j;
        for (int i2 = 0; i2 < nk; i2++) ob[i2] = (float)c4r[i2];
    }
}

// ---------------------------------------------------------------------------
extern "C" void kernel_launch(void* const* d_in, const int* in_sizes, int n_in,
                              void* d_out, int out_size) {
    int ci = 0, mi = 1;
    if (n_in >= 2 && in_sizes[0] == BATCH * N && in_sizes[1] == BATCH * N * N) {
        ci = 1; mi = 0;
    }
    const float*        costs = (const float*)d_in[ci];
    const unsigned int* mask  = (const unsigned int*)d_in[mi];
    float* out = (float*)d_out;

    nk_kernel<<<BATCH, 256>>>(mask);
    transpose_kernel<<<dim3(N / 32, N / 32, BATCH), dim3(32, 8)>>>(costs);
    solve_kernel<<<BATCH, 32>>>(out);
}

// round 5
// speedup vs baseline: 1.0282x; 1.0282x over previous
#include <cuda_runtime.h>
#include <cstdint>

#define BATCH 512
#define N 256
constexpr float FINF = 1e30f;

// Scratch: transposed + sanitized + pad-zeroed cost matrices (128 MiB, static).
__device__ float g_P[(size_t)BATCH * N * N];
__device__ int   g_nk[BATCH];

// order-preserving float->uint key (ascending); -0 canonicalized to +0 key
__device__ __forceinline__ unsigned fkey(float f) {
    unsigned b = __float_as_uint(f);
    unsigned k = (b & 0x80000000u) ? ~b : (b | 0x80000000u);
    k += (k == 0x7FFFFFFFu);  // -0 -> +0 (integer op, fast-math-proof)
    return k;
}
__device__ __forceinline__ float fkey_inv(unsigned k) {
    unsigned b = (k & 0x80000000u) ? (k ^ 0x80000000u) : ~k;
    return __uint_as_float(b);
}

// ---------------------------------------------------------------------------
// Kernel 1: n_k[b] = count of nonzero mask words (bool widened to i32 or f32).
// ---------------------------------------------------------------------------
__global__ void nk_kernel(const unsigned int* __restrict__ mask) {
    int b = blockIdx.x;
    int t = threadIdx.x;
    int v = (mask[b * N + t] != 0u) ? 1 : 0;
#pragma unroll
    for (int off = 16; off; off >>= 1) v += __shfl_xor_sync(0xffffffffu, v, off);
    __shared__ int s[8];
    if ((t & 31) == 0) s[t >> 5] = v;
    __syncthreads();
    if (t == 0) {
        int tot = 0;
#pragma unroll
        for (int w = 0; w < 8; w++) tot += s[w];
        g_nk[b] = tot;
    }
}

// ---------------------------------------------------------------------------
// Kernel 2: P[b][i][j] = sanitize(costs[b][j][i]) for i < n_k[b], else 0
// ---------------------------------------------------------------------------
__global__ void transpose_kernel(const float* __restrict__ costs) {
    __shared__ float tile[32][33];
    int b  = blockIdx.z;
    int i0 = blockIdx.x * 32;
    int j0 = blockIdx.y * 32;
    int tx = threadIdx.x, ty = threadIdx.y;  // 32 x 8
    const float* src = costs + (size_t)b * N * N;
    float*       dst = g_P   + (size_t)b * N * N;
#pragma unroll
    for (int s = 0; s < 32; s += 8) {
        float x = src[(size_t)(j0 + ty + s) * N + (i0 + tx)];
        unsigned bits = __float_as_uint(x);
        if ((bits & 0x7f800000u) == 0x7f800000u) x = 1e6f;  // nan or +-inf
        tile[ty + s][tx] = x;
    }
    __syncthreads();
    int nkb = g_nk[b];
#pragma unroll
    for (int s = 0; s < 32; s += 8) {
        int i = i0 + ty + s;
        dst[(size_t)i * N + (j0 + tx)] = (i < nkb) ? tile[tx][ty + s] : 0.0f;
    }
}

// ---------------------------------------------------------------------------
// Kernel 3: one warp per batch, JV shortest augmenting path.
// R3 skeleton: lane l owns columns j = l + 32t (coalesced LDG, conflict-free LDS).
// New: key-space argmin (IMNMX tree + 2x REDUX.SYNC.UMIN) + next-row prefetch.
// Float arithmetic order replicates the JAX reference exactly; key compares
// are order-isomorphic to float compares, ties -> smallest j (jnp argmin).
// Output written as float32 (harness materializes int indices as f32).
// ---------------------------------------------------------------------------
__global__ void __launch_bounds__(32) solve_kernel(float* __restrict__ out) {
    const int b    = blockIdx.x;
    const int lane = threadIdx.x;
    const float* P = g_P + (size_t)b * N * N;
    const int nk   = g_nk[b];
    const unsigned KINF = fkey(FINF);

    __shared__ float u[N];
    __shared__ int   c4r[N];
    __shared__ int   r4c[N];
    __shared__ float shS[N];
    __shared__ int   shP[N];

    float v[8];
#pragma unroll
    for (int t = 0; t < 8; t++) {
        int idx = lane + 32 * t;
        u[idx] = 0.0f; c4r[idx] = -1; r4c[idx] = -1; v[t] = 0.0f;
    }
    __syncwarp();

    // prefetch row 0
    float pf[8];
#pragma unroll
    for (int t = 0; t < 8; t++) pf[t] = P[lane + 32 * t];

    for (int cur = 0; cur < N; ++cur) {
        unsigned sk[8];   // shortest as monotone keys
        float    sf[8];   // shortest as exact floats (dual updates)
        int      prow[8];
#pragma unroll
        for (int t = 0; t < 8; t++) { sk[t] = KINF; sf[t] = FINF; prow[t] = -1; }
        unsigned scMask = 0, srMask = 0;
        int   i      = cur;
        float minval = 0.0f;
        int   sink;
        float cj[8];
#pragma unroll
        for (int t = 0; t < 8; t++) cj[t] = pf[t];

        while (true) {
            if ((i & 31) == lane) srMask |= 1u << (i >> 5);  // SR[i] = true
            float ui = u[i];

            unsigned mk[8];
#pragma unroll
            for (int t = 0; t < 8; t++) {
                if (!((scMask >> t) & 1u)) {
                    // exact reference op order: ((minval + cost) - u[i]) - v[j]
                    float r = ((minval + cj[t]) - ui) - v[t];
                    unsigned rk = fkey(r);
                    if (rk < sk[t]) { sk[t] = rk; sf[t] = r; prow[t] = i; }
                    mk[t] = sk[t];
                } else {
                    mk[t] = KINF;  // masked (SC)
                }
            }
            // per-lane min key: flat int-min tree (IMNMX, lat 4)
            unsigned a0 = min(mk[0], mk[1]), a1 = min(mk[2], mk[3]);
            unsigned a2 = min(mk[4], mk[5]), a3 = min(mk[6], mk[7]);
            unsigned m  = min(min(a0, a1), min(a2, a3));
            // first (smallest-j) slot achieving m; j = lane + 32t -> smallest t
            unsigned tmask = 0;
#pragma unroll
            for (int t = 0; t < 8; t++) tmask |= (mk[t] == m) ? (1u << t) : 0u;
            int myJ = lane + 32 * (__ffs(tmask) - 1);
            // cross-lane argmin: min key, then min j among tied lanes
            unsigned gmin = __reduce_min_sync(0xffffffffu, m);
            unsigned jc   = (m == gmin) ? (unsigned)myJ : 0xFFFFFFFFu;
            int jmin      = (int)__reduce_min_sync(0xffffffffu, jc);
            minval = fkey_inv(gmin);

            if ((jmin & 31) == lane) scMask |= 1u << (jmin >> 5);  // SC[jmin] = true
            int nxt = r4c[jmin];
            if (nxt < 0) { sink = jmin; break; }
            i = nxt;
            const float* Prow = P + (size_t)i * N;
#pragma unroll
            for (int t = 0; t < 8; t++) cj[t] = Prow[lane + 32 * t];
        }

        // prefetch next Dijkstra's first row (hidden behind epilogue)
        if (cur + 1 < N) {
            const float* Pn = P + (size_t)(cur + 1) * N;
#pragma unroll
            for (int t = 0; t < 8; t++) pf[t] = Pn[lane + 32 * t];
        }

        // dump per-column state (conflict-free STS)
#pragma unroll
        for (int t = 0; t < 8; t++) {
            int j = lane + 32 * t;
            shS[j] = sf[t];
            shP[j] = prow[t];
        }
        __syncwarp();

        // dual updates (reads c4r BEFORE augmentation, as in reference)
#pragma unroll
        for (int t = 0; t < 8; t++) {
            int row = lane + 32 * t;
            if (row == cur) {
                u[row] = u[row] + minval;
            } else if ((srMask >> t) & 1u) {
                int c  = c4r[row];
                u[row] = u[row] + (minval - shS[c]);
            }
            if ((scMask >> t) & 1u) v[t] = v[t] - (minval - sf[t]);
        }
        __syncwarp();

        // augment along alternating path back to cur (lane 0)
        if (lane == 0) {
            int j = sink;
            while (true) {
                int ii  = shP[j];
                r4c[j]  = ii;
                int jn  = c4r[ii];
                c4r[ii] = j;
                j = jn;
                if (ii == cur) break;
            }
        }
        __syncwarp();
    }

    // Output (float32): valid rows -> assigned column; padded rows -> unused
    // prediction indices ascending (reference's argsort fill).
    if (lane == 0) {
        float* ob = out + b * N;
        int cnt = 0;
        for (int j = 0; j < N; j++)
            if (r4c[j] >= nk) ob[nk + cnt++] = (float)j;
        for (int i2 = 0; i2 < nk; i2++) ob[i2] = (float)c4r[i2];
    }
}

// ---------------------------------------------------------------------------
extern "C" void kernel_launch(void* const* d_in, const int* in_sizes, int n_in,
                              void* d_out, int out_size) {
    int ci = 0, mi = 1;
    if (n_in >= 2 && in_sizes[0] == BATCH * N && in_sizes[1] == BATCH * N * N) {
        ci = 1; mi = 0;
    }
    const float*        costs = (const float*)d_in[ci];
    const unsigned int* mask  = (const unsigned int*)d_in[mi];
    float* out = (float*)d_out;

    nk_kernel<<<BATCH, 256>>>(mask);
    transpose_kernel<<<dim3(N / 32, N / 32, BATCH), dim3(32, 8)>>>(costs);
    solve_kernel<<<BATCH, 32>>>(out);
}

// round 6
// speedup vs baseline: 1.5386x; 1.4964x over previous
#include <cuda_runtime.h>
#include <cstdint>

#define BATCH 512
#define N 256
constexpr float FINF = 1e30f;

// Scratch: transposed + sanitized + pad-zeroed cost matrices (128 MiB, static).
__device__ float g_P[(size_t)BATCH * N * N];
__device__ int   g_nk[BATCH];

// smem index permutation: makes t-strided accesses (row = 8*lane + t)
// bank-conflict-free (sigma(8L+t) = 32t + L). Self-consistent everywhere.
__device__ __forceinline__ int sig(int x) { return ((x & 7) << 5) | (x >> 3); }

// ---------------------------------------------------------------------------
// Kernel 1: n_k[b] = count of nonzero mask words (bool widened to i32 or f32).
// ---------------------------------------------------------------------------
__global__ void nk_kernel(const unsigned int* __restrict__ mask) {
    int b = blockIdx.x;
    int t = threadIdx.x;
    int v = (mask[b * N + t] != 0u) ? 1 : 0;
#pragma unroll
    for (int off = 16; off; off >>= 1) v += __shfl_xor_sync(0xffffffffu, v, off);
    __shared__ int s[8];
    if ((t & 31) == 0) s[t >> 5] = v;
    __syncthreads();
    if (t == 0) {
        int tot = 0;
#pragma unroll
        for (int w = 0; w < 8; w++) tot += s[w];
        g_nk[b] = tot;
    }
}

// ---------------------------------------------------------------------------
// Kernel 2: P[b][i][j] = sanitize(costs[b][j][i]) for i < n_k[b], else 0
// ---------------------------------------------------------------------------
__global__ void transpose_kernel(const float* __restrict__ costs) {
    __shared__ float tile[32][33];
    int b  = blockIdx.z;
    int i0 = blockIdx.x * 32;
    int j0 = blockIdx.y * 32;
    int tx = threadIdx.x, ty = threadIdx.y;  // 32 x 8
    const float* src = costs + (size_t)b * N * N;
    float*       dst = g_P   + (size_t)b * N * N;
#pragma unroll
    for (int s = 0; s < 32; s += 8) {
        float x = src[(size_t)(j0 + ty + s) * N + (i0 + tx)];
        unsigned bits = __float_as_uint(x);
        if ((bits & 0x7f800000u) == 0x7f800000u) x = 1e6f;  // nan or +-inf
        tile[ty + s][tx] = x;
    }
    __syncthreads();
    int nkb = g_nk[b];
#pragma unroll
    for (int s = 0; s < 32; s += 8) {
        int i = i0 + ty + s;
        dst[(size_t)i * N + (j0 + tx)] = (i < nkb) ? tile[tx][ty + s] : 0.0f;
    }
}

// ---------------------------------------------------------------------------
// Kernel 3: one warp per batch, JV shortest augmenting path.
// Lane l owns columns j = 8l..8l+7 (2x LDG.128 row loads). Lowest tied lane
// == lowest j, so argmin = FMNMX value tree + ballot + ffs + 2 shfl_idx.
// All smem arrays indexed through sig() -> conflict-free t-loops.
// Float arithmetic order replicates the JAX reference exactly; strict-< scan
// and float == tie handling preserve jnp first-occurrence argmin semantics.
// ---------------------------------------------------------------------------
__global__ void __launch_bounds__(32) solve_kernel(float* __restrict__ out) {
    const int b    = blockIdx.x;
    const int lane = threadIdx.x;
    const float* P = g_P + (size_t)b * N * N;
    const int nk   = g_nk[b];

    __shared__ float u[N];    // sig-indexed
    __shared__ int   c4r[N];  // sig-indexed
    __shared__ int   r4c[N];  // sig-indexed
    __shared__ float shS[N];  // sig-indexed
    __shared__ int   shP[N];  // sig-indexed

    float v[8];
#pragma unroll
    for (int t = 0; t < 8; t++) {
        int s = 32 * t + lane;       // = sig(8*lane + t)
        u[s] = 0.0f; c4r[s] = -1; r4c[s] = -1; v[t] = 0.0f;
    }
    __syncwarp();

    for (int cur = 0; cur < N; ++cur) {
        float shortest[8];
        int   prow[8];
#pragma unroll
        for (int t = 0; t < 8; t++) { shortest[t] = FINF; prow[t] = -1; }
        unsigned scMask = 0, srMask = 0;
        int   i      = cur;
        float minval = 0.0f;
        int   sink;

        const float4* p4 = (const float4*)(P + (size_t)i * N) + lane * 2;
        float4 c0 = p4[0], c1 = p4[1];

        while (true) {
            if ((i >> 3) == lane) srMask |= 1u << (i & 7);   // SR[i] = true
            float ui = u[sig(i)];
            float cj[8] = {c0.x, c0.y, c0.z, c0.w, c1.x, c1.y, c1.z, c1.w};

            float mk[8];
#pragma unroll
            for (int t = 0; t < 8; t++) {
                if (!((scMask >> t) & 1u)) {
                    // exact reference op order: ((minval + cost) - u[i]) - v[j]
                    float r = ((minval + cj[t]) - ui) - v[t];
                    if (r < shortest[t]) { shortest[t] = r; prow[t] = i; }  // strict <
                    mk[t] = shortest[t];
                } else {
                    mk[t] = FINF;  // masked (SC)
                }
            }
            // per-lane min value: flat FMNMX tree
            float a0 = fminf(mk[0], mk[1]), a1 = fminf(mk[2], mk[3]);
            float a2 = fminf(mk[4], mk[5]), a3 = fminf(mk[6], mk[7]);
            float m  = fminf(fminf(a0, a1), fminf(a2, a3));
            // first slot achieving m (float ==: +-0 tie like jnp, first wins)
            unsigned tm = 0;
#pragma unroll
            for (int t = 0; t < 8; t++) tm |= (mk[t] == m) ? (1u << t) : 0u;
            int myJ = 8 * lane + (__ffs(tm) - 1);
            // warp min value (FMNMX shuffle tree, no predicates)
            float g = m;
#pragma unroll
            for (int off = 16; off; off >>= 1)
                g = fminf(g, __shfl_xor_sync(0xffffffffu, g, off));
            unsigned tied = __ballot_sync(0xffffffffu, m == g);
            int src  = __ffs(tied) - 1;       // lowest tied lane == lowest j
            int jmin = __shfl_sync(0xffffffffu, myJ, src);
            minval   = __shfl_sync(0xffffffffu, m, src);

            if ((jmin >> 3) == lane) scMask |= 1u << (jmin & 7);  // SC[jmin]
            int nxt = r4c[sig(jmin)];
            if (nxt < 0) { sink = jmin; break; }
            i = nxt;
            const float4* q4 = (const float4*)(P + (size_t)i * N) + lane * 2;
            c0 = q4[0]; c1 = q4[1];
        }

        // dump per-column state (sig layout -> conflict-free)
#pragma unroll
        for (int t = 0; t < 8; t++) {
            int s = 32 * t + lane;   // = sig(8*lane + t)
            shS[s] = shortest[t];
            shP[s] = prow[t];
        }
        __syncwarp();

        // dual updates (reads c4r BEFORE augmentation, as in reference)
#pragma unroll
        for (int t = 0; t < 8; t++) {
            int row = 8 * lane + t;
            int s   = 32 * t + lane;  // sig(row)
            if (row == cur) {
                u[s] = u[s] + minval;
            } else if ((srMask >> t) & 1u) {
                int c = c4r[s];
                u[s]  = u[s] + (minval - shS[sig(c)]);
            }
            if ((scMask >> t) & 1u) v[t] = v[t] - (minval - shortest[t]);
        }
        __syncwarp();

        // augment along alternating path back to cur (lane 0, scalar)
        if (lane == 0) {
            int j = sink;
            while (true) {
                int sj = sig(j);
                int ii = shP[sj];
                r4c[sj] = ii;
                int si = sig(ii);
                int jn = c4r[si];
                c4r[si] = j;
                j = jn;
                if (ii == cur) break;
            }
        }
        __syncwarp();
    }

    // Output (float32): valid rows -> assigned column; padded rows -> unused
    // prediction indices ascending (reference's argsort fill).
    if (lane == 0) {
        float* ob = out + b * N;
        int cnt = 0;
        for (int j = 0; j < N; j++)
            if (r4c[sig(j)] >= nk) ob[nk + cnt++] = (float)j;
        for (int i2 = 0; i2 < nk; i2++) ob[i2] = (float)c4r[sig(i2)];
    }
}

// ---------------------------------------------------------------------------
extern "C" void kernel_launch(void* const* d_in, const int* in_sizes, int n_in,
                              void* d_out, int out_size) {
    int ci = 0, mi = 1;
    if (n_in >= 2 && in_sizes[0] == BATCH * N && in_sizes[1] == BATCH * N * N) {
        ci = 1; mi = 0;
    }
    const float*        costs = (const float*)d_in[ci];
    const unsigned int* mask  = (const unsigned int*)d_in[mi];
    float* out = (float*)d_out;

    nk_kernel<<<BATCH, 256>>>(mask);
    transpose_kernel<<<dim3(N / 32, N / 32, BATCH), dim3(32, 8)>>>(costs);
    solve_kernel<<<BATCH, 32>>>(out);
}

// round 7
// speedup vs baseline: 47.3490x; 30.7745x over previous
#include <cuda_runtime.h>
#include <cstdint>

#define BATCH 512
#define N 256
constexpr float FINF = 1e30f;

// Scratch: transposed + sanitized cost matrices (128 MiB, static).
__device__ float g_P[(size_t)BATCH * N * N];
__device__ int   g_nk[BATCH];

// smem index permutation: sigma(8L+t) = 32t + L -> t-strided loops conflict-free.
__device__ __forceinline__ int sig(int x) { return ((x & 7) << 5) | (x >> 3); }

// ---------------------------------------------------------------------------
// Kernel 1: n_k[b] = count of nonzero mask words (bool widened to i32 or f32).
// ---------------------------------------------------------------------------
__global__ void nk_kernel(const unsigned int* __restrict__ mask) {
    int b = blockIdx.x;
    int t = threadIdx.x;
    int v = (mask[b * N + t] != 0u) ? 1 : 0;
#pragma unroll
    for (int off = 16; off; off >>= 1) v += __shfl_xor_sync(0xffffffffu, v, off);
    __shared__ int s[8];
    if ((t & 31) == 0) s[t >> 5] = v;
    __syncthreads();
    if (t == 0) {
        int tot = 0;
#pragma unroll
        for (int w = 0; w < 8; w++) tot += s[w];
        g_nk[b] = tot;
    }
}

// ---------------------------------------------------------------------------
// Kernel 2: P[b][i][j] = sanitize(costs[b][j][i])  (nan/±inf -> 1e6)
// (rows >= n_k are never read by the rectangular solver; no zeroing needed)
// ---------------------------------------------------------------------------
__global__ void transpose_kernel(const float* __restrict__ costs) {
    __shared__ float tile[32][33];
    int b  = blockIdx.z;
    int i0 = blockIdx.x * 32;
    int j0 = blockIdx.y * 32;
    int tx = threadIdx.x, ty = threadIdx.y;  // 32 x 8
    const float* src = costs + (size_t)b * N * N;
    float*       dst = g_P   + (size_t)b * N * N;
#pragma unroll
    for (int s = 0; s < 32; s += 8) {
        float x = src[(size_t)(j0 + ty + s) * N + (i0 + tx)];
        unsigned bits = __float_as_uint(x);
        if ((bits & 0x7f800000u) == 0x7f800000u) x = 1e6f;  // nan or +-inf
        tile[ty + s][tx] = x;
    }
    __syncthreads();
#pragma unroll
    for (int s = 0; s < 32; s += 8) {
        int i = i0 + ty + s;
        dst[(size_t)i * N + (j0 + tx)] = tile[tx][ty + s];
    }
}

// ---------------------------------------------------------------------------
// Kernel 3: one warp per batch, RECTANGULAR (n_k x N) JV shortest augmenting
// path. Padded rows (constant 0 cost) cannot change the real rows' optimal
// assignment, and the output only needs real rows' columns + the used-set,
// so we solve only rows 0..n_k-1. With ~half the columns never assigned,
// each Dijkstra terminates after very few pops.
// Lane l owns columns j = 8l..8l+7 (2x LDG.128). Lowest tied lane == lowest j.
// All smem arrays sig()-permuted -> conflict-free t-loops.
// ---------------------------------------------------------------------------
__global__ void __launch_bounds__(32) solve_kernel(float* __restrict__ out) {
    const int b    = blockIdx.x;
    const int lane = threadIdx.x;
    const float* P = g_P + (size_t)b * N * N;
    const int nk   = g_nk[b];

    __shared__ float u[N];    // sig-indexed (rows)
    __shared__ int   c4r[N];  // sig-indexed (rows)
    __shared__ int   r4c[N];  // sig-indexed (cols)
    __shared__ float shS[N];  // sig-indexed (cols)
    __shared__ int   shP[N];  // sig-indexed (cols)

    float v[8];
#pragma unroll
    for (int t = 0; t < 8; t++) {
        int s = 32 * t + lane;       // = sig(8*lane + t)
        u[s] = 0.0f; c4r[s] = -1; r4c[s] = -1; v[t] = 0.0f;
    }
    __syncwarp();

    for (int cur = 0; cur < nk; ++cur) {
        float shortest[8];
        int   prow[8];
#pragma unroll
        for (int t = 0; t < 8; t++) { shortest[t] = FINF; prow[t] = -1; }
        unsigned scMask = 0, srMask = 0;
        int   i      = cur;
        float minval = 0.0f;
        int   sink;

        const float4* p4 = (const float4*)(P + (size_t)i * N) + lane * 2;
        float4 c0 = p4[0], c1 = p4[1];

        while (true) {
            if ((i >> 3) == lane) srMask |= 1u << (i & 7);   // SR[i] = true
            float ui = u[sig(i)];
            float cj[8] = {c0.x, c0.y, c0.z, c0.w, c1.x, c1.y, c1.z, c1.w};

            float mk[8];
#pragma unroll
            for (int t = 0; t < 8; t++) {
                if (!((scMask >> t) & 1u)) {
                    // reference op order: ((minval + cost) - u[i]) - v[j]
                    float r = ((minval + cj[t]) - ui) - v[t];
                    if (r < shortest[t]) { shortest[t] = r; prow[t] = i; }
                    mk[t] = shortest[t];
                } else {
                    mk[t] = FINF;  // masked (SC)
                }
            }
            // per-lane min (flat FMNMX tree), first slot achieving it
            float a0 = fminf(mk[0], mk[1]), a1 = fminf(mk[2], mk[3]);
            float a2 = fminf(mk[4], mk[5]), a3 = fminf(mk[6], mk[7]);
            float m  = fminf(fminf(a0, a1), fminf(a2, a3));
            unsigned tm = 0;
#pragma unroll
            for (int t = 0; t < 8; t++) tm |= (mk[t] == m) ? (1u << t) : 0u;
            int myJ = 8 * lane + (__ffs(tm) - 1);
            // warp min value + lowest tied lane (== lowest j)
            float g = m;
#pragma unroll
            for (int off = 16; off; off >>= 1)
                g = fminf(g, __shfl_xor_sync(0xffffffffu, g, off));
            unsigned tied = __ballot_sync(0xffffffffu, m == g);
            int src  = __ffs(tied) - 1;
            int jmin = __shfl_sync(0xffffffffu, myJ, src);
            minval   = __shfl_sync(0xffffffffu, m, src);

            if ((jmin >> 3) == lane) scMask |= 1u << (jmin & 7);  // SC[jmin]
            int nxt = r4c[sig(jmin)];
            if (nxt < 0) { sink = jmin; break; }
            i = nxt;
            const float4* q4 = (const float4*)(P + (size_t)i * N) + lane * 2;
            c0 = q4[0]; c1 = q4[1];
        }

        // dump per-column state (conflict-free)
#pragma unroll
        for (int t = 0; t < 8; t++) {
            int s = 32 * t + lane;   // = sig(8*lane + t)
            shS[s] = shortest[t];
            shP[s] = prow[t];
        }
        __syncwarp();

        // dual updates (reads c4r BEFORE augmentation)
#pragma unroll
        for (int t = 0; t < 8; t++) {
            int row = 8 * lane + t;
            int s   = 32 * t + lane;  // sig(row)
            if (row == cur) {
                u[s] = u[s] + minval;
            } else if ((srMask >> t) & 1u) {
                int c = c4r[s];
                u[s]  = u[s] + (minval - shS[sig(c)]);
            }
            if ((scMask >> t) & 1u) v[t] = v[t] - (minval - shortest[t]);
        }
        __syncwarp();

        // augment along alternating path back to cur (lane 0)
        if (lane == 0) {
            int j = sink;
            while (true) {
                int sj = sig(j);
                int ii = shP[sj];
                r4c[sj] = ii;
                int si = sig(ii);
                int jn = c4r[si];
                c4r[si] = j;
                j = jn;
                if (ii == cur) break;
            }
        }
        __syncwarp();
    }

    // Output (float32): rows < nk -> assigned column; rows >= nk -> unassigned
    // columns ascending (reference's argsort fill over the used-set).
    if (lane == 0) {
        float* ob = out + b * N;
        int cnt = 0;
        for (int j = 0; j < N; j++)
            if (r4c[sig(j)] < 0) ob[nk + cnt++] = (float)j;  // unused, ascending
        for (int i2 = 0; i2 < nk; i2++) ob[i2] = (float)c4r[sig(i2)];
    }
}

// ---------------------------------------------------------------------------
extern "C" void kernel_launch(void* const* d_in, const int* in_sizes, int n_in,
                              void* d_out, int out_size) {
    int ci = 0, mi = 1;
    if (n_in >= 2 && in_sizes[0] == BATCH * N && in_sizes[1] == BATCH * N * N) {
        ci = 1; mi = 0;
    }
    const float*        costs = (const float*)d_in[ci];
    const unsigned int* mask  = (const unsigned int*)d_in[mi];
    float* out = (float*)d_out;

    nk_kernel<<<BATCH, 256>>>(mask);
    transpose_kernel<<<dim3(N / 32, N / 32, BATCH), dim3(32, 8)>>>(costs);
    solve_kernel<<<BATCH, 32>>>(out);
}

// round 8
// speedup vs baseline: 65.1170x; 1.3753x over previous
#include <cuda_runtime.h>
#include <cstdint>

#define BATCH 512
#define N 256
constexpr float FINF = 1e30f;

// Scratch: transposed + sanitized cost matrices (128 MiB, static).
__device__ float g_P[(size_t)BATCH * N * N];
__device__ int   g_nk[BATCH];

// smem index permutation: sigma(8L+t) = 32t + L -> t-strided loops conflict-free.
__device__ __forceinline__ int sig(int x) { return ((x & 7) << 5) | (x >> 3); }

// ---------------------------------------------------------------------------
// Kernel 1: n_k[b] = count of nonzero mask words (bool widened to i32 or f32).
// ---------------------------------------------------------------------------
__global__ void nk_kernel(const unsigned int* __restrict__ mask) {
    int b = blockIdx.x;
    int t = threadIdx.x;
    int v = (mask[b * N + t] != 0u) ? 1 : 0;
#pragma unroll
    for (int off = 16; off; off >>= 1) v += __shfl_xor_sync(0xffffffffu, v, off);
    __shared__ int s[8];
    if ((t & 31) == 0) s[t >> 5] = v;
    __syncthreads();
    if (t == 0) {
        int tot = 0;
#pragma unroll
        for (int w = 0; w < 8; w++) tot += s[w];
        g_nk[b] = tot;
    }
}

// ---------------------------------------------------------------------------
// Kernel 2: P[b][i][j] = sanitize(costs[b][j][i]) for i < n_k[b] only.
// Tiles whose entire output row range is >= n_k are skipped: ~half the
// traffic, and the useful P footprint (~64 MB) then fits in L2.
// ---------------------------------------------------------------------------
__global__ void transpose_kernel(const float* __restrict__ costs) {
    __shared__ float tile[32][33];
    int b  = blockIdx.z;
    int i0 = blockIdx.x * 32;   // output rows (object index)
    int nkb = g_nk[b];
    if (i0 >= nkb) return;      // rows never read by rectangular solver
    int j0 = blockIdx.y * 32;
    int tx = threadIdx.x, ty = threadIdx.y;  // 32 x 8
    const float* src = costs + (size_t)b * N * N;
    float*       dst = g_P   + (size_t)b * N * N;
#pragma unroll
    for (int s = 0; s < 32; s += 8) {
        float x = src[(size_t)(j0 + ty + s) * N + (i0 + tx)];
        unsigned bits = __float_as_uint(x);
        if ((bits & 0x7f800000u) == 0x7f800000u) x = 1e6f;  // nan or +-inf
        tile[ty + s][tx] = x;
    }
    __syncthreads();
#pragma unroll
    for (int s = 0; s < 32; s += 8) {
        int i = i0 + ty + s;
        dst[(size_t)i * N + (j0 + tx)] = tile[tx][ty + s];
    }
}

// ---------------------------------------------------------------------------
// Kernel 3: one warp per batch, RECTANGULAR (n_k x N) JV shortest augmenting
// path. Lane l owns columns j = 8l..8l+7 (2x LDG.128). Lowest tied lane ==
// lowest j. smem sig()-permuted -> conflict-free t-loops. Next Dijkstra's
// first row is prefetched during the epilogue.
// ---------------------------------------------------------------------------
__global__ void __launch_bounds__(32) solve_kernel(float* __restrict__ out) {
    const int b    = blockIdx.x;
    const int lane = threadIdx.x;
    const float* P = g_P + (size_t)b * N * N;
    const int nk   = g_nk[b];

    __shared__ float u[N];    // sig-indexed (rows)
    __shared__ int   c4r[N];  // sig-indexed (rows)
    __shared__ int   r4c[N];  // sig-indexed (cols)
    __shared__ float shS[N];  // sig-indexed (cols)
    __shared__ int   shP[N];  // sig-indexed (cols)

    float v[8];
#pragma unroll
    for (int t = 0; t < 8; t++) {
        int s = 32 * t + lane;       // = sig(8*lane + t)
        u[s] = 0.0f; c4r[s] = -1; r4c[s] = -1; v[t] = 0.0f;
    }
    __syncwarp();

    // prefetch row 0
    float4 pf0, pf1;
    if (nk > 0) {
        const float4* p4 = (const float4*)P + lane * 2;
        pf0 = p4[0]; pf1 = p4[1];
    }

    for (int cur = 0; cur < nk; ++cur) {
        float shortest[8];
        int   prow[8];
#pragma unroll
        for (int t = 0; t < 8; t++) { shortest[t] = FINF; prow[t] = -1; }
        unsigned scMask = 0, srMask = 0;
        int   i      = cur;
        float minval = 0.0f;
        int   sink;
        float4 c0 = pf0, c1 = pf1;

        while (true) {
            if ((i >> 3) == lane) srMask |= 1u << (i & 7);   // SR[i] = true
            float ui = u[sig(i)];
            float cj[8] = {c0.x, c0.y, c0.z, c0.w, c1.x, c1.y, c1.z, c1.w};

            float mk[8];
#pragma unroll
            for (int t = 0; t < 8; t++) {
                if (!((scMask >> t) & 1u)) {
                    // reference op order: ((minval + cost) - u[i]) - v[j]
                    float r = ((minval + cj[t]) - ui) - v[t];
                    if (r < shortest[t]) { shortest[t] = r; prow[t] = i; }
                    mk[t] = shortest[t];
                } else {
                    mk[t] = FINF;  // masked (SC)
                }
            }
            // per-lane min (flat FMNMX tree), first slot achieving it
            float a0 = fminf(mk[0], mk[1]), a1 = fminf(mk[2], mk[3]);
            float a2 = fminf(mk[4], mk[5]), a3 = fminf(mk[6], mk[7]);
            float m  = fminf(fminf(a0, a1), fminf(a2, a3));
            unsigned tm = 0;
#pragma unroll
            for (int t = 0; t < 8; t++) tm |= (mk[t] == m) ? (1u << t) : 0u;
            int myJ = 8 * lane + (__ffs(tm) - 1);
            // warp min value + lowest tied lane (== lowest j)
            float g = m;
#pragma unroll
            for (int off = 16; off; off >>= 1)
                g = fminf(g, __shfl_xor_sync(0xffffffffu, g, off));
            unsigned tied = __ballot_sync(0xffffffffu, m == g);
            int src  = __ffs(tied) - 1;
            int jmin = __shfl_sync(0xffffffffu, myJ, src);
            minval   = __shfl_sync(0xffffffffu, m, src);

            if ((jmin >> 3) == lane) scMask |= 1u << (jmin & 7);  // SC[jmin]
            int nxt = r4c[sig(jmin)];
            if (nxt < 0) { sink = jmin; break; }
            i = nxt;
            const float4* q4 = (const float4*)(P + (size_t)i * N) + lane * 2;
            c0 = q4[0]; c1 = q4[1];
        }

        // prefetch next Dijkstra's first row (latency hidden by epilogue)
        if (cur + 1 < nk) {
            const float4* q4 = (const float4*)(P + (size_t)(cur + 1) * N) + lane * 2;
            pf0 = q4[0]; pf1 = q4[1];
        }

        // dump per-column state (conflict-free)
#pragma unroll
        for (int t = 0; t < 8; t++) {
            int s = 32 * t + lane;   // = sig(8*lane + t)
            shS[s] = shortest[t];
            shP[s] = prow[t];
        }
        __syncwarp();

        // dual updates (reads c4r BEFORE augmentation)
#pragma unroll
        for (int t = 0; t < 8; t++) {
            int row = 8 * lane + t;
            int s   = 32 * t + lane;  // sig(row)
            if (row == cur) {
                u[s] = u[s] + minval;
            } else if ((srMask >> t) & 1u) {
                int c = c4r[s];
                u[s]  = u[s] + (minval - shS[sig(c)]);
            }
            if ((scMask >> t) & 1u) v[t] = v[t] - (minval - shortest[t]);
        }
        __syncwarp();

        // augment along alternating path back to cur (lane 0)
        if (lane == 0) {
            int j = sink;
            while (true) {
                int sj = sig(j);
                int ii = shP[sj];
                r4c[sj] = ii;
                int si = sig(ii);
                int jn = c4r[si];
                c4r[si] = j;
                j = jn;
                if (ii == cur) break;
            }
        }
        __syncwarp();
    }

    // Output (float32), all lanes in parallel:
    //   rows < nk          -> assigned column
    //   rows nk..N-1       -> unassigned columns, ascending
    {
        float* ob = out + b * N;
        // per-lane unused info (lane owns cols j = 8l..8l+7, contiguous)
        unsigned umask = 0;
        int uc = 0;
#pragma unroll
        for (int t = 0; t < 8; t++) {
            int j = 8 * lane + t;
            bool unused = (r4c[sig(j)] < 0);
            umask |= unused ? (1u << t) : 0u;
            uc += unused ? 1 : 0;
        }
        // exclusive prefix sum of uc over lanes (ascending lane == ascending j)
        int incl = uc;
#pragma unroll
        for (int off = 1; off < 32; off <<= 1) {
            int o = __shfl_up_sync(0xffffffffu, incl, off);
            if (lane >= off) incl += o;
        }
        int pos = nk + (incl - uc);
#pragma unroll
        for (int t = 0; t < 8; t++) {
            if ((umask >> t) & 1u) ob[pos++] = (float)(8 * lane + t);
        }
        // assigned rows
#pragma unroll
        for (int t = 0; t < 8; t++) {
            int row = 8 * lane + t;
            if (row < nk) ob[row] = (float)c4r[32 * t + lane];  // c4r[sig(row)]
        }
    }
}

// ---------------------------------------------------------------------------
extern "C" void kernel_launch(void* const* d_in, const int* in_sizes, int n_in,
                              void* d_out, int out_size) {
    int ci = 0, mi = 1;
    if (n_in >= 2 && in_sizes[0] == BATCH * N && in_sizes[1] == BATCH * N * N) {
        ci = 1; mi = 0;
    }
    const float*        costs = (const float*)d_in[ci];
    const unsigned int* mask  = (const unsigned int*)d_in[mi];
    float* out = (float*)d_out;

    nk_kernel<<<BATCH, 256>>>(mask);
    transpose_kernel<<<dim3(N / 32, N / 32, BATCH), dim3(32, 8)>>>(costs);
    solve_kernel<<<BATCH, 32>>>(out);
}